// round 1
// baseline (speedup 1.0000x reference)
#include <cuda_runtime.h>
#include <math.h>

// ---------------- problem-size caps (fixed by setup_inputs) ----------------
#define MAXN 50000
#define MAXE 800000

// ---------------- device scratch (no allocation allowed) -------------------
__device__ int   g_deg[MAXN];        // src out-degree
__device__ int   g_cnt[MAXN];        // dst in-degree (CSR row counts)
__device__ int   g_cur[MAXN];        // fill cursors
__device__ int   g_roff[MAXN + 1];   // CSR row offsets (by dst)
__device__ int   g_csrc[MAXE];       // CSR column (src node)
__device__ float g_cw[MAXE];         // CSR edge weight
__device__ float g_dis[MAXN];        // deg^{-1/2}
__device__ float g_xc[(size_t)MAXN * 384];    // cheb concat [N, 3F]
__device__ float g_gate[(size_t)MAXN * 768];  // gate pre-activations [N, 3H]
__device__ float g_h[(size_t)MAXN * 256];     // layer output
__device__ float g_h2[(size_t)MAXN * 256];    // post-linear output
__device__ float g_wB[384 * 384];    // rearranged gate weights [3F, 3H]
__device__ float g_wbias[768];       // combined gate bias

// ---------------- graph preprocessing ----------------

__global__ void k_degree(const int* __restrict__ src, const int* __restrict__ dst, int E) {
    int e = blockIdx.x * blockDim.x + threadIdx.x;
    if (e >= E) return;
    atomicAdd(&g_deg[src[e]], 1);
    atomicAdd(&g_cnt[dst[e]], 1);
}

__global__ void k_dis(int n) {
    int i = blockIdx.x * blockDim.x + threadIdx.x;
    if (i >= n) return;
    int d = g_deg[i];
    g_dis[i] = d > 0 ? rsqrtf((float)d) : 0.0f;
}

// single-block exclusive scan of g_cnt -> g_roff
__global__ void k_scan(int n) {
    __shared__ int ssum[1024];
    int tid = threadIdx.x;
    const int T = 1024;
    int chunk = (n + T - 1) / T;
    int beg = tid * chunk;
    int end = beg + chunk; if (end > n) end = n;
    int s = 0;
    for (int i = beg; i < end; i++) s += g_cnt[i];
    ssum[tid] = s;
    __syncthreads();
    // Hillis-Steele inclusive scan
    for (int off = 1; off < T; off <<= 1) {
        int v = (tid >= off) ? ssum[tid - off] : 0;
        __syncthreads();
        ssum[tid] += v;
        __syncthreads();
    }
    int run = (tid > 0) ? ssum[tid - 1] : 0;
    for (int i = beg; i < end; i++) { g_roff[i] = run; run += g_cnt[i]; }
    if (tid == T - 1) g_roff[n] = ssum[T - 1];
}

__global__ void k_fill(const int* __restrict__ src, const int* __restrict__ dst, int E) {
    int e = blockIdx.x * blockDim.x + threadIdx.x;
    if (e >= E) return;
    int s = src[e], d = dst[e];
    int pos = g_roff[d] + atomicAdd(&g_cur[d], 1);
    g_csrc[pos] = s;
    g_cw[pos] = -g_dis[s] * g_dis[d];
}

// ---------------- SpMV: y[dst] = sum_e w*x[src]  (optionally 2*acc - x0) ---

template <int F>
__global__ void k_spmv(const float* __restrict__ X, int xp,
                       const float* __restrict__ X0, int x0p,
                       float* __restrict__ Y, int yp, int cheb2) {
    int row = blockIdx.x;
    int f = threadIdx.x;  // F threads
    int j0 = g_roff[row], j1 = g_roff[row + 1];
    float acc = 0.0f;
    for (int j = j0; j < j1; j++) {
        acc += g_cw[j] * X[(size_t)g_csrc[j] * xp + f];
    }
    float v = cheb2 ? (2.0f * acc - X0[(size_t)row * x0p + f]) : acc;
    Y[(size_t)row * yp + f] = v;
}

// F=3 variant: one thread per row
__global__ void k_spmv3(const float* __restrict__ X, int xp,
                        const float* __restrict__ X0, int x0p,
                        float* __restrict__ Y, int yp, int cheb2, int n) {
    int row = blockIdx.x * blockDim.x + threadIdx.x;
    if (row >= n) return;
    int j0 = g_roff[row], j1 = g_roff[row + 1];
    float a0 = 0.f, a1 = 0.f, a2 = 0.f;
    for (int j = j0; j < j1; j++) {
        int s = g_csrc[j];
        float w = g_cw[j];
        const float* xr = X + (size_t)s * xp;
        a0 += w * xr[0]; a1 += w * xr[1]; a2 += w * xr[2];
    }
    if (cheb2) {
        const float* x0 = X0 + (size_t)row * x0p;
        a0 = 2.f * a0 - x0[0]; a1 = 2.f * a1 - x0[1]; a2 = 2.f * a2 - x0[2];
    }
    float* yr = Y + (size_t)row * yp;
    yr[0] = a0; yr[1] = a1; yr[2] = a2;
}

__global__ void k_copy(const float* __restrict__ src, int sp,
                       float* __restrict__ dst, int dp, int n, int f) {
    int i = blockIdx.x * blockDim.x + threadIdx.x;
    int tot = n * f;
    if (i >= tot) return;
    int r = i / f, c = i % f;
    dst[(size_t)r * dp + c] = src[(size_t)r * sp + c];
}

// ---------------- weight rearrangement ----------------
// Wx: [4, K, F, H]; gates used: 0 (i), 2 (c), 3 (o) -> g' = 0,1,2
// B[(k*F+i), g'*H+o] = Wx[gate, k, i, o];  bias[g'*H+o] = bx+bh+b

__global__ void k_prep_w(const float* __restrict__ Wx, float* __restrict__ B,
                         int K, int F, int H) {
    int idx = blockIdx.x * blockDim.x + threadIdx.x;
    int tot = K * F * 3 * H;
    if (idx >= tot) return;
    int cols = 3 * H;
    int row = idx / cols;        // k*F + i
    int col = idx % cols;
    int gp = col / H, o = col % H;
    int gate = (gp == 0) ? 0 : (gp + 1);   // 0,2,3
    int k = row / F, i = row % F;
    B[idx] = Wx[(((size_t)gate * K + k) * F + i) * H + o];
}

__global__ void k_prep_bias(const float* __restrict__ bx, const float* __restrict__ bh,
                            const float* __restrict__ b, float* __restrict__ biasOut, int H) {
    int col = blockIdx.x * blockDim.x + threadIdx.x;
    if (col >= 3 * H) return;
    int gp = col / H, o = col % H;
    int gate = (gp == 0) ? 0 : (gp + 1);
    biasOut[col] = bx[gate * H + o] + bh[gate * H + o] + b[gate * H + o];
}

// ---------------- SGEMM: C[M,N] = A[M,K] @ B[K,N] + bias, optional lrelu ---
// BM=BN=128, BK=8, 256 threads, 8x8 per thread

template <int ACT>
__global__ __launch_bounds__(256) void sgemm128(
    const float* __restrict__ A, const float* __restrict__ B,
    const float* __restrict__ bias, float* __restrict__ C,
    int M, int N, int K) {
    __shared__ float As[8][128];
    __shared__ float Bs[8][128];
    int tid = threadIdx.x;
    int bm = blockIdx.y * 128, bn = blockIdx.x * 128;
    int tr = tid / 16, tc = tid % 16;

    float acc[8][8];
#pragma unroll
    for (int i = 0; i < 8; i++)
#pragma unroll
        for (int j = 0; j < 8; j++) acc[i][j] = 0.f;

    int arow = tid / 2;
    int akb = (tid % 2) * 4;
    int bk = tid / 32;
    int bnb = (tid % 32) * 4;

    for (int k0 = 0; k0 < K; k0 += 8) {
#pragma unroll
        for (int i = 0; i < 4; i++) {
            int kk = k0 + akb + i;
            int r = bm + arow;
            float v = 0.f;
            if (r < M && kk < K) v = A[(size_t)r * K + kk];
            As[akb + i][arow] = v;
        }
#pragma unroll
        for (int i = 0; i < 4; i++) {
            int kk = k0 + bk;
            int c = bn + bnb + i;
            float v = 0.f;
            if (kk < K && c < N) v = B[(size_t)kk * N + c];
            Bs[bk][bnb + i] = v;
        }
        __syncthreads();
#pragma unroll
        for (int kk = 0; kk < 8; kk++) {
            float4 a0 = *reinterpret_cast<const float4*>(&As[kk][tr * 8]);
            float4 a1 = *reinterpret_cast<const float4*>(&As[kk][tr * 8 + 4]);
            float4 b0 = *reinterpret_cast<const float4*>(&Bs[kk][tc * 8]);
            float4 b1 = *reinterpret_cast<const float4*>(&Bs[kk][tc * 8 + 4]);
            float av[8] = {a0.x, a0.y, a0.z, a0.w, a1.x, a1.y, a1.z, a1.w};
            float bv[8] = {b0.x, b0.y, b0.z, b0.w, b1.x, b1.y, b1.z, b1.w};
#pragma unroll
            for (int i = 0; i < 8; i++)
#pragma unroll
                for (int j = 0; j < 8; j++) acc[i][j] += av[i] * bv[j];
        }
        __syncthreads();
    }
#pragma unroll
    for (int i = 0; i < 8; i++) {
        int r = bm + tr * 8 + i;
        if (r >= M) continue;
#pragma unroll
        for (int j = 0; j < 8; j++) {
            int c = bn + tc * 8 + j;
            if (c >= N) continue;
            float v = acc[i][j] + (bias ? bias[c] : 0.f);
            if (ACT == 1) v = v > 0.f ? v : 0.1f * v;
            C[(size_t)r * N + c] = v;
        }
    }
}

// ---------------- LSTM gate fusion ----------------
// G row: [i-pre | c-pre | o-pre(without wc term)], length 3H. out = lrelu(O*tanh(C))

__device__ __forceinline__ float sigf(float x) { return 1.0f / (1.0f + expf(-x)); }

__global__ void k_gates(const float* __restrict__ G, const float* __restrict__ wcO,
                        float* __restrict__ Y, int n, int H) {
    int idx = blockIdx.x * blockDim.x + threadIdx.x;
    if (idx >= n * H) return;
    int r = idx / H, o = idx % H;
    const float* g = G + (size_t)r * 3 * H;
    float I = sigf(g[o]);
    float T = tanhf(g[H + o]);
    float Cv = I * T;
    float O = sigf(g[2 * H + o] + wcO[o] * Cv);
    float y = O * tanhf(Cv);
    Y[(size_t)r * H + o] = y > 0.f ? y : 0.1f * y;
}

// ---------------- final small GEMM: [N,64]@[64,3] + bias -------------------

__global__ void k_lin3(const float* __restrict__ Hin, const float* __restrict__ W,
                       const float* __restrict__ b, float* __restrict__ out, int n) {
    __shared__ float w[64 * 3];
    if (threadIdx.x < 192) w[threadIdx.x] = W[threadIdx.x];
    __syncthreads();
    int r = blockIdx.x * blockDim.x + threadIdx.x;
    if (r >= n) return;
    float a0 = b[0], a1 = b[1], a2 = b[2];
    const float* h = Hin + (size_t)r * 64;
#pragma unroll
    for (int k = 0; k < 64; k++) {
        float hv = h[k];
        a0 += hv * w[k * 3 + 0];
        a1 += hv * w[k * 3 + 1];
        a2 += hv * w[k * 3 + 2];
    }
    float* o = out + (size_t)r * 3;
    o[0] = a0; o[1] = a1; o[2] = a2;
}

// ---------------- host orchestration ----------------

static inline int ceildiv(int a, int b) { return (a + b - 1) / b; }

extern "C" void kernel_launch(void* const* d_in, const int* in_sizes, int n_in,
                              void* d_out, int out_size) {
    const float* x = (const float*)d_in[0];
    const int* ei = (const int*)d_in[1];
    int N = in_sizes[0] / 3;
    int E = in_sizes[1] / 2;
    const int* src = ei;
    const int* dst = ei + E;

    // layer params
    const float* l1_Wx = (const float*)d_in[2];
    const float* l1_bx = (const float*)d_in[3];
    const float* l1_bh = (const float*)d_in[5];
    const float* l1_wc = (const float*)d_in[6];
    const float* l1_b  = (const float*)d_in[7];
    const float* l2_Wx = (const float*)d_in[8];
    const float* l2_bx = (const float*)d_in[9];
    const float* l2_bh = (const float*)d_in[11];
    const float* l2_wc = (const float*)d_in[12];
    const float* l2_b  = (const float*)d_in[13];
    const float* l3_Wx = (const float*)d_in[14];
    const float* l3_bx = (const float*)d_in[15];
    const float* l3_bh = (const float*)d_in[17];
    const float* l3_wc = (const float*)d_in[18];
    const float* l3_b  = (const float*)d_in[19];
    const float* lin1_W = (const float*)d_in[20];
    const float* lin1_b = (const float*)d_in[21];
    const float* lin2_W = (const float*)d_in[22];
    const float* lin2_b = (const float*)d_in[23];
    const float* lin3_W = (const float*)d_in[24];
    const float* lin3_b = (const float*)d_in[25];
    float* out = (float*)d_out;

    // symbol addresses
    void* p;
    cudaGetSymbolAddress(&p, g_deg);   int* deg = (int*)p;
    cudaGetSymbolAddress(&p, g_cnt);   int* cnt = (int*)p;
    cudaGetSymbolAddress(&p, g_cur);   int* cur = (int*)p;
    cudaGetSymbolAddress(&p, g_xc);    float* xc = (float*)p;
    cudaGetSymbolAddress(&p, g_gate);  float* G = (float*)p;
    cudaGetSymbolAddress(&p, g_h);     float* Hbuf = (float*)p;
    cudaGetSymbolAddress(&p, g_h2);    float* H2 = (float*)p;
    cudaGetSymbolAddress(&p, g_wB);    float* wB = (float*)p;
    cudaGetSymbolAddress(&p, g_wbias); float* wbias = (float*)p;

    cudaStream_t s = 0;

    // ---- graph preprocessing (CSR by dst, shared across all 3 layers) ----
    cudaMemsetAsync(deg, 0, N * sizeof(int), s);
    cudaMemsetAsync(cnt, 0, N * sizeof(int), s);
    cudaMemsetAsync(cur, 0, N * sizeof(int), s);
    k_degree<<<ceildiv(E, 256), 256, 0, s>>>(src, dst, E);
    k_dis<<<ceildiv(N, 256), 256, 0, s>>>(N);
    k_scan<<<1, 1024, 0, s>>>(N);
    k_fill<<<ceildiv(E, 256), 256, 0, s>>>(src, dst, E);

    // ================= layer 1 (F=3, H=256) =================
    {
        const int F = 3, H = 256, K = 3;
        // cheb concat into xc [N, 9]
        k_copy<<<ceildiv(N * F, 256), 256, 0, s>>>(x, F, xc, 3 * F, N, F);
        k_spmv3<<<ceildiv(N, 256), 256, 0, s>>>(x, F, x, F, xc + F, 3 * F, 0, N);
        k_spmv3<<<ceildiv(N, 256), 256, 0, s>>>(xc + F, 3 * F, x, F, xc + 2 * F, 3 * F, 1, N);
        // weights
        k_prep_w<<<ceildiv(K * F * 3 * H, 256), 256, 0, s>>>(l1_Wx, wB, K, F, H);
        k_prep_bias<<<ceildiv(3 * H, 256), 256, 0, s>>>(l1_bx, l1_bh, l1_b, wbias, H);
        // gate GEMM [N,9]@[9,768]
        dim3 grid(ceildiv(3 * H, 128), ceildiv(N, 128));
        sgemm128<0><<<grid, 256, 0, s>>>(xc, wB, wbias, G, N, 3 * H, K * F);
        k_gates<<<ceildiv(N * H, 256), 256, 0, s>>>(G, l1_wc + 2 * H, Hbuf, N, H);
        // lin1: [N,256]@[256,128] + lrelu
        dim3 g2(ceildiv(128, 128), ceildiv(N, 128));
        sgemm128<1><<<g2, 256, 0, s>>>(Hbuf, lin1_W, lin1_b, H2, N, 128, 256);
    }

    // ================= layer 2 (F=128, H=128) =================
    {
        const int F = 128, H = 128, K = 3;
        k_copy<<<ceildiv(N * F, 256), 256, 0, s>>>(H2, F, xc, 3 * F, N, F);
        k_spmv<F><<<N, F, 0, s>>>(H2, F, H2, F, xc + F, 3 * F, 0);
        k_spmv<F><<<N, F, 0, s>>>(xc + F, 3 * F, H2, F, xc + 2 * F, 3 * F, 1);
        k_prep_w<<<ceildiv(K * F * 3 * H, 256), 256, 0, s>>>(l2_Wx, wB, K, F, H);
        k_prep_bias<<<ceildiv(3 * H, 256), 256, 0, s>>>(l2_bx, l2_bh, l2_b, wbias, H);
        dim3 grid(ceildiv(3 * H, 128), ceildiv(N, 128));
        sgemm128<0><<<grid, 256, 0, s>>>(xc, wB, wbias, G, N, 3 * H, K * F);
        k_gates<<<ceildiv(N * H, 256), 256, 0, s>>>(G, l2_wc + 2 * H, Hbuf, N, H);
        // lin2: [N,128]@[128,64] + lrelu
        dim3 g2(ceildiv(64, 128), ceildiv(N, 128));
        sgemm128<1><<<g2, 256, 0, s>>>(Hbuf, lin2_W, lin2_b, H2, N, 64, 128);
    }

    // ================= layer 3 (F=64, H=64) =================
    {
        const int F = 64, H = 64, K = 3;
        k_copy<<<ceildiv(N * F, 256), 256, 0, s>>>(H2, F, xc, 3 * F, N, F);
        k_spmv<F><<<N, F, 0, s>>>(H2, F, H2, F, xc + F, 3 * F, 0);
        k_spmv<F><<<N, F, 0, s>>>(xc + F, 3 * F, H2, F, xc + 2 * F, 3 * F, 1);
        k_prep_w<<<ceildiv(K * F * 3 * H, 256), 256, 0, s>>>(l3_Wx, wB, K, F, H);
        k_prep_bias<<<ceildiv(3 * H, 256), 256, 0, s>>>(l3_bx, l3_bh, l3_b, wbias, H);
        dim3 grid(ceildiv(3 * H, 128), ceildiv(N, 128));
        sgemm128<0><<<grid, 256, 0, s>>>(xc, wB, wbias, G, N, 3 * H, K * F);
        k_gates<<<ceildiv(N * H, 256), 256, 0, s>>>(G, l3_wc + 2 * H, Hbuf, N, H);
        // lin3: [N,64]@[64,3]
        k_lin3<<<ceildiv(N, 256), 256, 0, s>>>(Hbuf, lin3_W, lin3_b, out, N);
    }
}

// round 3
// speedup vs baseline: 1.6019x; 1.6019x over previous
#include <cuda_runtime.h>
#include <cuda_bf16.h>
#include <math.h>
#include <stdint.h>

// ---------------- problem-size caps (fixed by setup_inputs) ----------------
#define MAXN 50000
#define NPADMAX 50048   // MAXN rounded up to 128

// ---------------- device scratch (no allocation allowed) -------------------
__device__ int   g_deg[MAXN];
__device__ int   g_cnt[MAXN];
__device__ int   g_cur[MAXN];
__device__ int   g_roff[MAXN + 1];
__device__ int   g_csrc[800000];
__device__ float g_cw[800000];
__device__ float g_dis[MAXN];
__device__ float g_xc[(size_t)MAXN * 384];     // cheb concat [N, 3F] fp32
__device__ float g_gate[(size_t)MAXN * 768];   // gate pre-activations fp32
__device__ float g_h[(size_t)MAXN * 256];      // layer3 gconv output fp32
__device__ float g_h2[(size_t)MAXN * 256];     // post-linear output fp32
__device__ float g_wbias[768];                 // combined gate bias
__device__ __align__(256) __nv_bfloat16 g_abuf[(size_t)NPADMAX * 1152]; // split A
__device__ __align__(256) __nv_bfloat16 g_bbuf[768 * 1152];             // split B

// ====================== graph preprocessing ================================

__global__ void k_degree(const int* __restrict__ src, const int* __restrict__ dst, int E) {
    int e = blockIdx.x * blockDim.x + threadIdx.x;
    if (e >= E) return;
    atomicAdd(&g_deg[src[e]], 1);
    atomicAdd(&g_cnt[dst[e]], 1);
}

__global__ void k_dis(int n) {
    int i = blockIdx.x * blockDim.x + threadIdx.x;
    if (i >= n) return;
    int d = g_deg[i];
    g_dis[i] = d > 0 ? rsqrtf((float)d) : 0.0f;
}

__global__ void k_scan(int n) {
    __shared__ int ssum[1024];
    int tid = threadIdx.x;
    const int T = 1024;
    int chunk = (n + T - 1) / T;
    int beg = tid * chunk;
    int end = beg + chunk; if (end > n) end = n;
    int s = 0;
    for (int i = beg; i < end; i++) s += g_cnt[i];
    ssum[tid] = s;
    __syncthreads();
    for (int off = 1; off < T; off <<= 1) {
        int v = (tid >= off) ? ssum[tid - off] : 0;
        __syncthreads();
        ssum[tid] += v;
        __syncthreads();
    }
    int run = (tid > 0) ? ssum[tid - 1] : 0;
    for (int i = beg; i < end; i++) { g_roff[i] = run; run += g_cnt[i]; }
    if (tid == T - 1) g_roff[n] = ssum[T - 1];
}

__global__ void k_fill(const int* __restrict__ src, const int* __restrict__ dst, int E) {
    int e = blockIdx.x * blockDim.x + threadIdx.x;
    if (e >= E) return;
    int s = src[e], d = dst[e];
    int pos = g_roff[d] + atomicAdd(&g_cur[d], 1);
    g_csrc[pos] = s;
    g_cw[pos] = -g_dis[s] * g_dis[d];
}

// ====================== SpMV (Chebyshev propagation) =======================

template <int F>
__global__ void k_spmv(const float* __restrict__ X, int xp,
                       const float* __restrict__ X0, int x0p,
                       float* __restrict__ Y, int yp, int cheb2) {
    int row = blockIdx.x;
    int f = threadIdx.x;
    int j0 = g_roff[row], j1 = g_roff[row + 1];
    float acc = 0.0f;
    for (int j = j0; j < j1; j++)
        acc += g_cw[j] * X[(size_t)g_csrc[j] * xp + f];
    float v = cheb2 ? (2.0f * acc - X0[(size_t)row * x0p + f]) : acc;
    Y[(size_t)row * yp + f] = v;
}

__global__ void k_spmv3(const float* __restrict__ X, int xp,
                        const float* __restrict__ X0, int x0p,
                        float* __restrict__ Y, int yp, int cheb2, int n) {
    int row = blockIdx.x * blockDim.x + threadIdx.x;
    if (row >= n) return;
    int j0 = g_roff[row], j1 = g_roff[row + 1];
    float a0 = 0.f, a1 = 0.f, a2 = 0.f;
    for (int j = j0; j < j1; j++) {
        int s = g_csrc[j];
        float w = g_cw[j];
        const float* xr = X + (size_t)s * xp;
        a0 += w * xr[0]; a1 += w * xr[1]; a2 += w * xr[2];
    }
    if (cheb2) {
        const float* x0 = X0 + (size_t)row * x0p;
        a0 = 2.f * a0 - x0[0]; a1 = 2.f * a1 - x0[1]; a2 = 2.f * a2 - x0[2];
    }
    float* yr = Y + (size_t)row * yp;
    yr[0] = a0; yr[1] = a1; yr[2] = a2;
}

__global__ void k_copy(const float* __restrict__ src, int sp,
                       float* __restrict__ dst, int dp, int n, int f) {
    int i = blockIdx.x * blockDim.x + threadIdx.x;
    if (i >= n * f) return;
    int r = i / f, c = i % f;
    dst[(size_t)r * dp + c] = src[(size_t)r * sp + c];
}

// ====================== bf16 split preparation =============================

__device__ __forceinline__ void bsplit(float x, __nv_bfloat16& hi, __nv_bfloat16& lo) {
    hi = __float2bfloat16_rn(x);
    lo = __float2bfloat16_rn(x - __bfloat162float(hi));
}

// A' = [hi | hi | lo], rows padded to npad with zeros. Kp multiple of 16.
__global__ void k_split_A(const float* __restrict__ X, int Kin, int Kp,
                          int n, int npad, __nv_bfloat16* __restrict__ A) {
    int idx = blockIdx.x * blockDim.x + threadIdx.x;
    if (idx >= npad * Kp) return;
    int r = idx / Kp, k = idx % Kp;
    float x = (r < n && k < Kin) ? X[(size_t)r * Kin + k] : 0.0f;
    __nv_bfloat16 hi, lo; bsplit(x, hi, lo);
    size_t base = (size_t)r * 3 * Kp;
    A[base + k] = hi;
    A[base + Kp + k] = hi;
    A[base + 2 * Kp + k] = lo;
}

// gate weights: B'[n=gp*H+o, blocks hi|lo|hi of Wx[gate,kc,f,o]], gates {0,2,3}
__global__ void k_split_Bgate(const float* __restrict__ Wx, int F, int H, int Kp,
                              __nv_bfloat16* __restrict__ B) {
    int idx = blockIdx.x * blockDim.x + threadIdx.x;
    if (idx >= 3 * H * Kp) return;
    int nrow = idx / Kp, kk = idx % Kp;
    int gp = nrow / H, o = nrow % H;
    int gate = (gp == 0) ? 0 : (gp + 1);
    float w = 0.0f;
    if (kk < 3 * F) {
        int kc = kk / F, f = kk % F;
        w = Wx[(((size_t)gate * 3 + kc) * F + f) * H + o];
    }
    __nv_bfloat16 hi, lo; bsplit(w, hi, lo);
    size_t base = (size_t)nrow * 3 * Kp;
    B[base + kk] = hi;
    B[base + Kp + kk] = lo;
    B[base + 2 * Kp + kk] = hi;
}

// linear weights W[Kin, Hout]: B'[n, k'] blocks hi|lo|hi of W[k', n]
__global__ void k_split_Blin(const float* __restrict__ W, int Kin, int Hout, int Kp,
                             __nv_bfloat16* __restrict__ B) {
    int idx = blockIdx.x * blockDim.x + threadIdx.x;
    if (idx >= Hout * Kp) return;
    int nrow = idx / Kp, kk = idx % Kp;
    float w = (kk < Kin) ? W[(size_t)kk * Hout + nrow] : 0.0f;
    __nv_bfloat16 hi, lo; bsplit(w, hi, lo);
    size_t base = (size_t)nrow * 3 * Kp;
    B[base + kk] = hi;
    B[base + Kp + kk] = lo;
    B[base + 2 * Kp + kk] = hi;
}

__global__ void k_prep_bias(const float* __restrict__ bx, const float* __restrict__ bh,
                            const float* __restrict__ b, float* __restrict__ biasOut, int H) {
    int col = blockIdx.x * blockDim.x + threadIdx.x;
    if (col >= 3 * H) return;
    int gp = col / H, o = col % H;
    int gate = (gp == 0) ? 0 : (gp + 1);
    biasOut[col] = bx[gate * H + o] + bh[gate * H + o] + b[gate * H + o];
}

// ====================== mma.sync bf16 GEMM =================================
// C[M, Nc] (+bias, opt lrelu) = A'[Mpad, K3] @ B'[Nc, K3]^T (both K-major bf16)
// CTA tile 128x64, BK=32, 8 warps (4m x 2n), warp tile 32x32 via m16n8k16.
// SMEM rows padded to 80B to avoid ldmatrix bank conflicts. cp.async pipelined.

#define CP16(dst, src) \
    asm volatile("cp.async.ca.shared.global [%0], [%1], 16;\n" :: "r"(dst), "l"(src))
#define CP_COMMIT() asm volatile("cp.async.commit_group;\n" ::: "memory")
#define CP_WAIT1()  asm volatile("cp.async.wait_group 1;\n" ::: "memory")
#define CP_WAIT0()  asm volatile("cp.async.wait_group 0;\n" ::: "memory")

__device__ __forceinline__ uint32_t smem_u32(const void* p) {
    uint32_t a;
    asm("{ .reg .u64 t; cvta.to.shared.u64 t, %1; cvt.u32.u64 %0, t; }"
        : "=r"(a) : "l"(p));
    return a;
}

__device__ __forceinline__ void ldm_x4(uint32_t* r, uint32_t addr) {
    asm volatile("ldmatrix.sync.aligned.m8n8.x4.shared.b16 {%0,%1,%2,%3}, [%4];"
                 : "=r"(r[0]), "=r"(r[1]), "=r"(r[2]), "=r"(r[3]) : "r"(addr));
}

__device__ __forceinline__ void mma16816(float* c, const uint32_t* a, const uint32_t* b) {
    asm volatile(
        "mma.sync.aligned.m16n8k16.row.col.f32.bf16.bf16.f32 "
        "{%0,%1,%2,%3}, {%4,%5,%6,%7}, {%8,%9}, {%0,%1,%2,%3};"
        : "+f"(c[0]), "+f"(c[1]), "+f"(c[2]), "+f"(c[3])
        : "r"(a[0]), "r"(a[1]), "r"(a[2]), "r"(a[3]), "r"(b[0]), "r"(b[1]));
}

__global__ __launch_bounds__(256) void gemm_mma(
    const __nv_bfloat16* __restrict__ A, const __nv_bfloat16* __restrict__ B,
    const float* __restrict__ bias, float* __restrict__ C,
    int M, int K3, int Nc, int act) {
    // stage: A 128 rows x 80B = 10240B ; B 64 rows x 80B = 5120B
    __shared__ __align__(16) char sA[2][128 * 80];
    __shared__ __align__(16) char sB[2][64 * 80];

    const int tid = threadIdx.x;
    const int wid = tid >> 5;
    const int lane = tid & 31;
    const int wm = wid & 3;      // warp m index (0..3)
    const int wn = wid >> 2;     // warp n index (0..1)
    const int bm = blockIdx.x << 7;
    const int bn = blockIdx.y << 6;

    const uint32_t sA0 = smem_u32(sA);
    const uint32_t sB0 = smem_u32(sB);

    float acc[2][4][4];
#pragma unroll
    for (int i = 0; i < 2; i++)
#pragma unroll
        for (int j = 0; j < 4; j++)
#pragma unroll
            for (int k = 0; k < 4; k++) acc[i][j][k] = 0.f;

    // load indices
    const int ar0 = tid >> 1;                 // A rows: 2 chunks/thread
    const int as0 = (tid & 1) * 2;            // A segs {0,1} or {2,3}
    const int br = tid >> 2, bs = tid & 3;    // B: 1 chunk/thread

    const int nK = K3 >> 5;

    // prologue: stage 0
    {
        int kc = 0;
#pragma unroll
        for (int i = 0; i < 2; i++) {
            int seg = as0 + i;
            uint32_t d = sA0 + ar0 * 80 + seg * 16;
            const char* g = (const char*)A + ((size_t)(bm + ar0) * K3 + kc) * 2 + seg * 16;
            CP16(d, g);
        }
        uint32_t d = sB0 + br * 80 + bs * 16;
        const char* g = (const char*)B + ((size_t)(bn + br) * K3 + kc) * 2 + bs * 16;
        CP16(d, g);
        CP_COMMIT();
    }

    for (int kt = 0; kt < nK; kt++) {
        int st = kt & 1;
        if (kt + 1 < nK) {
            int st1 = (kt + 1) & 1;
            int kc = (kt + 1) << 5;
#pragma unroll
            for (int i = 0; i < 2; i++) {
                int seg = as0 + i;
                uint32_t d = sA0 + st1 * (128 * 80) + ar0 * 80 + seg * 16;
                const char* g = (const char*)A + ((size_t)(bm + ar0) * K3 + kc) * 2 + seg * 16;
                CP16(d, g);
            }
            uint32_t d = sB0 + st1 * (64 * 80) + br * 80 + bs * 16;
            const char* g = (const char*)B + ((size_t)(bn + br) * K3 + kc) * 2 + bs * 16;
            CP16(d, g);
            CP_COMMIT();
            CP_WAIT1();
        } else {
            CP_WAIT0();
        }
        __syncthreads();

        // fragments
        uint32_t a[2][2][4];   // [kk][mt][4]
        uint32_t b[2][4][2];   // [kk][nt][2]
        uint32_t aBase = sA0 + st * (128 * 80);
        uint32_t bBase = sB0 + st * (64 * 80);
#pragma unroll
        for (int kk = 0; kk < 2; kk++) {
#pragma unroll
            for (int mt = 0; mt < 2; mt++) {
                uint32_t addr = aBase + (wm * 32 + mt * 16 + (lane & 15)) * 80
                              + kk * 32 + (lane >> 4) * 16;
                ldm_x4(a[kk][mt], addr);
            }
#pragma unroll
            for (int j = 0; j < 2; j++) {
                uint32_t r[4];
                uint32_t addr = bBase + (wn * 32 + j * 16 + (lane & 15)) * 80
                              + kk * 32 + (lane >> 4) * 16;
                ldm_x4(r, addr);
                b[kk][2 * j][0] = r[0]; b[kk][2 * j][1] = r[2];
                b[kk][2 * j + 1][0] = r[1]; b[kk][2 * j + 1][1] = r[3];
            }
        }
#pragma unroll
        for (int kk = 0; kk < 2; kk++)
#pragma unroll
            for (int mt = 0; mt < 2; mt++)
#pragma unroll
                for (int nt = 0; nt < 4; nt++)
                    mma16816(acc[mt][nt], a[kk][mt], b[kk][nt]);
        __syncthreads();
    }

    // epilogue
    const int gid = lane >> 2, tig = lane & 3;
#pragma unroll
    for (int mt = 0; mt < 2; mt++) {
#pragma unroll
        for (int half = 0; half < 2; half++) {
            int row = bm + wm * 32 + mt * 16 + half * 8 + gid;
            if (row >= M) continue;
#pragma unroll
            for (int nt = 0; nt < 4; nt++) {
                int col = bn + wn * 32 + nt * 8 + tig * 2;
                float v0 = acc[mt][nt][2 * half + 0] + bias[col];
                float v1 = acc[mt][nt][2 * half + 1] + bias[col + 1];
                if (act) {
                    v0 = v0 > 0.f ? v0 : 0.1f * v0;
                    v1 = v1 > 0.f ? v1 : 0.1f * v1;
                }
                *reinterpret_cast<float2*>(&C[(size_t)row * Nc + col]) = make_float2(v0, v1);
            }
        }
    }
}

// ====================== LSTM gate fusion ===================================

__device__ __forceinline__ float sigf(float x) { return 1.0f / (1.0f + expf(-x)); }

__device__ __forceinline__ float gate_eval(const float* g, const float* wcO, int H, int o) {
    float I = sigf(g[o]);
    float T = tanhf(g[H + o]);
    float Cv = I * T;
    float O = sigf(g[2 * H + o] + wcO[o] * Cv);
    float y = O * tanhf(Cv);
    return y > 0.f ? y : 0.1f * y;   // leaky relu fused
}

__global__ void k_gates(const float* __restrict__ G, const float* __restrict__ wcO,
                        float* __restrict__ Y, int n, int H) {
    int idx = blockIdx.x * blockDim.x + threadIdx.x;
    if (idx >= n * H) return;
    int r = idx / H, o = idx % H;
    Y[(size_t)r * H + o] = gate_eval(G + (size_t)r * 3 * H, wcO, H, o);
}

// gates -> bf16-split A' directly (layers 1, 2; Kp == H)
__global__ void k_gates_split(const float* __restrict__ G, const float* __restrict__ wcO,
                              __nv_bfloat16* __restrict__ A, int n, int npad, int H) {
    int idx = blockIdx.x * blockDim.x + threadIdx.x;
    if (idx >= npad * H) return;
    int r = idx / H, o = idx % H;
    float y = 0.0f;
    if (r < n) y = gate_eval(G + (size_t)r * 3 * H, wcO, H, o);
    __nv_bfloat16 hi, lo; bsplit(y, hi, lo);
    size_t base = (size_t)r * 3 * H;
    A[base + o] = hi;
    A[base + H + o] = hi;
    A[base + 2 * H + o] = lo;
}

// ====================== final small GEMM [N,64]@[64,3] =====================

__global__ void k_lin3(const float* __restrict__ Hin, const float* __restrict__ W,
                       const float* __restrict__ b, float* __restrict__ out, int n) {
    __shared__ float w[64 * 3];
    if (threadIdx.x < 192) w[threadIdx.x] = W[threadIdx.x];
    __syncthreads();
    int r = blockIdx.x * blockDim.x + threadIdx.x;
    if (r >= n) return;
    float a0 = b[0], a1 = b[1], a2 = b[2];
    const float* h = Hin + (size_t)r * 64;
#pragma unroll
    for (int k = 0; k < 64; k++) {
        float hv = h[k];
        a0 += hv * w[k * 3 + 0];
        a1 += hv * w[k * 3 + 1];
        a2 += hv * w[k * 3 + 2];
    }
    float* o = out + (size_t)r * 3;
    o[0] = a0; o[1] = a1; o[2] = a2;
}

// ====================== host orchestration =================================

static inline int ceildiv(int a, int b) { return (a + b - 1) / b; }

extern "C" void kernel_launch(void* const* d_in, const int* in_sizes, int n_in,
                              void* d_out, int out_size) {
    const float* x = (const float*)d_in[0];
    const int* ei = (const int*)d_in[1];
    int N = in_sizes[0] / 3;
    int E = in_sizes[1] / 2;
    const int* src = ei;
    const int* dst = ei + E;
    int Npad = (N + 127) & ~127;
    int Mt = Npad / 128;

    const float* l1_Wx = (const float*)d_in[2];
    const float* l1_bx = (const float*)d_in[3];
    const float* l1_bh = (const float*)d_in[5];
    const float* l1_wc = (const float*)d_in[6];
    const float* l1_b  = (const float*)d_in[7];
    const float* l2_Wx = (const float*)d_in[8];
    const float* l2_bx = (const float*)d_in[9];
    const float* l2_bh = (const float*)d_in[11];
    const float* l2_wc = (const float*)d_in[12];
    const float* l2_b  = (const float*)d_in[13];
    const float* l3_Wx = (const float*)d_in[14];
    const float* l3_bx = (const float*)d_in[15];
    const float* l3_bh = (const float*)d_in[17];
    const float* l3_wc = (const float*)d_in[18];
    const float* l3_b  = (const float*)d_in[19];
    const float* lin1_W = (const float*)d_in[20];
    const float* lin1_b = (const float*)d_in[21];
    const float* lin2_W = (const float*)d_in[22];
    const float* lin2_b = (const float*)d_in[23];
    const float* lin3_W = (const float*)d_in[24];
    const float* lin3_b = (const float*)d_in[25];
    float* out = (float*)d_out;

    void* p;
    cudaGetSymbolAddress(&p, g_deg);   int* deg = (int*)p;
    cudaGetSymbolAddress(&p, g_cnt);   int* cnt = (int*)p;
    cudaGetSymbolAddress(&p, g_cur);   int* cur = (int*)p;
    cudaGetSymbolAddress(&p, g_xc);    float* xc = (float*)p;
    cudaGetSymbolAddress(&p, g_gate);  float* G = (float*)p;
    cudaGetSymbolAddress(&p, g_h);     float* Hbuf = (float*)p;
    cudaGetSymbolAddress(&p, g_h2);    float* H2 = (float*)p;
    cudaGetSymbolAddress(&p, g_wbias); float* wbias = (float*)p;
    cudaGetSymbolAddress(&p, g_abuf);  __nv_bfloat16* abuf = (__nv_bfloat16*)p;
    cudaGetSymbolAddress(&p, g_bbuf);  __nv_bfloat16* bbuf = (__nv_bfloat16*)p;

    cudaStream_t s = 0;

    // ---- graph preprocessing ----
    cudaMemsetAsync(deg, 0, N * sizeof(int), s);
    cudaMemsetAsync(cnt, 0, N * sizeof(int), s);
    cudaMemsetAsync(cur, 0, N * sizeof(int), s);
    k_degree<<<ceildiv(E, 256), 256, 0, s>>>(src, dst, E);
    k_dis<<<ceildiv(N, 256), 256, 0, s>>>(N);
    k_scan<<<1, 1024, 0, s>>>(N);
    k_fill<<<ceildiv(E, 256), 256, 0, s>>>(src, dst, E);

    // ================= layer 1 (F=3, H=256) =================
    {
        const int F = 3, H = 256, Kp = 32, K3 = 96;
        k_copy<<<ceildiv(N * F, 256), 256, 0, s>>>(x, F, xc, 3 * F, N, F);
        k_spmv3<<<ceildiv(N, 256), 256, 0, s>>>(x, F, x, F, xc + F, 3 * F, 0, N);
        k_spmv3<<<ceildiv(N, 256), 256, 0, s>>>(xc + F, 3 * F, x, F, xc + 2 * F, 3 * F, 1, N);
        k_split_A<<<ceildiv(Npad * Kp, 256), 256, 0, s>>>(xc, 3 * F, Kp, N, Npad, abuf);
        k_split_Bgate<<<ceildiv(3 * H * Kp, 256), 256, 0, s>>>(l1_Wx, F, H, Kp, bbuf);
        k_prep_bias<<<ceildiv(3 * H, 256), 256, 0, s>>>(l1_bx, l1_bh, l1_b, wbias, H);
        gemm_mma<<<dim3(Mt, (3 * H) / 64), 256, 0, s>>>(abuf, bbuf, wbias, G, N, K3, 3 * H, 0);
        k_gates_split<<<ceildiv(Npad * H, 256), 256, 0, s>>>(G, l1_wc + 2 * H, abuf, N, Npad, H);
        // lin1: [N,256]@[256,128] + lrelu   (Kp=256, K3=768)
        k_split_Blin<<<ceildiv(128 * 256, 256), 256, 0, s>>>(lin1_W, 256, 128, 256, bbuf);
        gemm_mma<<<dim3(Mt, 2), 256, 0, s>>>(abuf, bbuf, lin1_b, H2, N, 768, 128, 1);
    }

    // ================= layer 2 (F=128, H=128) =================
    {
        const int F = 128, H = 128, Kp = 384, K3 = 1152;
        k_copy<<<ceildiv(N * F, 256), 256, 0, s>>>(H2, F, xc, 3 * F, N, F);
        k_spmv<F><<<N, F, 0, s>>>(H2, F, H2, F, xc + F, 3 * F, 0);
        k_spmv<F><<<N, F, 0, s>>>(xc + F, 3 * F, H2, F, xc + 2 * F, 3 * F, 1);
        k_split_A<<<ceildiv(Npad * Kp, 256), 256, 0, s>>>(xc, 3 * F, Kp, N, Npad, abuf);
        k_split_Bgate<<<ceildiv(3 * H * Kp, 256), 256, 0, s>>>(l2_Wx, F, H, Kp, bbuf);
        k_prep_bias<<<ceildiv(3 * H, 256), 256, 0, s>>>(l2_bx, l2_bh, l2_b, wbias, H);
        gemm_mma<<<dim3(Mt, (3 * H) / 64), 256, 0, s>>>(abuf, bbuf, wbias, G, N, K3, 3 * H, 0);
        k_gates_split<<<ceildiv(Npad * H, 256), 256, 0, s>>>(G, l2_wc + 2 * H, abuf, N, Npad, H);
        // lin2: [N,128]@[128,64] + lrelu   (Kp=128, K3=384)
        k_split_Blin<<<ceildiv(64 * 128, 256), 256, 0, s>>>(lin2_W, 128, 64, 128, bbuf);
        gemm_mma<<<dim3(Mt, 1), 256, 0, s>>>(abuf, bbuf, lin2_b, H2, N, 384, 64, 1);
    }

    // ================= layer 3 (F=64, H=64) =================
    {
        const int F = 64, H = 64, Kp = 192, K3 = 576;
        k_copy<<<ceildiv(N * F, 256), 256, 0, s>>>(H2, F, xc, 3 * F, N, F);
        k_spmv<F><<<N, F, 0, s>>>(H2, F, H2, F, xc + F, 3 * F, 0);
        k_spmv<F><<<N, F, 0, s>>>(xc + F, 3 * F, H2, F, xc + 2 * F, 3 * F, 1);
        k_split_A<<<ceildiv(Npad * Kp, 256), 256, 0, s>>>(xc, 3 * F, Kp, N, Npad, abuf);
        k_split_Bgate<<<ceildiv(3 * H * Kp, 256), 256, 0, s>>>(l3_Wx, F, H, Kp, bbuf);
        k_prep_bias<<<ceildiv(3 * H, 256), 256, 0, s>>>(l3_bx, l3_bh, l3_b, wbias, H);
        gemm_mma<<<dim3(Mt, (3 * H) / 64), 256, 0, s>>>(abuf, bbuf, wbias, G, N, K3, 3 * H, 0);
        k_gates<<<ceildiv(N * H, 256), 256, 0, s>>>(G, l3_wc + 2 * H, Hbuf, N, H);
        k_lin3<<<ceildiv(N, 256), 256, 0, s>>>(Hbuf, lin3_W, lin3_b, out, N);
    }
}

// round 4
// speedup vs baseline: 2.1662x; 1.3522x over previous
#include <cuda_runtime.h>
#include <cuda_bf16.h>
#include <math.h>
#include <stdint.h>

// ---------------- problem-size caps (fixed by setup_inputs) ----------------
#define MAXN 50000
#define NPADMAX 50048   // MAXN rounded up to 128

// ---------------- device scratch (no allocation allowed) -------------------
__device__ int   g_deg[MAXN];
__device__ int   g_cnt[MAXN];
__device__ int   g_cur[MAXN];
__device__ int   g_roff[MAXN + 1];
__device__ int   g_csrc[800000];
__device__ float g_cw[800000];
__device__ float g_dis[MAXN];
__device__ float g_xc[(size_t)MAXN * 384];     // dense Tx1 scratch [N, F]
__device__ float g_gate[(size_t)MAXN * 768];   // gate pre-activations fp32
__device__ float g_h[(size_t)MAXN * 64];       // layer3 gconv output fp32
__device__ float g_h2[(size_t)MAXN * 128];     // post-linear output (dense)
__device__ float g_wbias[1344];                // combined gate biases (l1|l2|l3)
__device__ __align__(256) __nv_bfloat16 g_bufA[(size_t)NPADMAX * 768]; // gconv A2
__device__ __align__(256) __nv_bfloat16 g_bufB[(size_t)NPADMAX * 512]; // lin A2
__device__ __align__(256) __nv_bfloat16 g_bbuf[524288];                // all B2

// B buffer element offsets (each region is rows x 2*Kp)
#define O_B1  0        // l1 gate: 768 x 64
#define O_B2  49152    // l2 gate: 384 x 768
#define O_B3  344064   // l3 gate: 192 x 384
#define O_BL1 417792   // lin1: 128 x 512
#define O_BL2 483328   // lin2: 64 x 256

// ====================== graph preprocessing ================================

__global__ void k_degree(const int* __restrict__ src, const int* __restrict__ dst, int E) {
    int e = blockIdx.x * blockDim.x + threadIdx.x;
    if (e >= E) return;
    atomicAdd(&g_deg[src[e]], 1);
    atomicAdd(&g_cnt[dst[e]], 1);
}

__global__ void k_dis(int n) {
    int i = blockIdx.x * blockDim.x + threadIdx.x;
    if (i >= n) return;
    int d = g_deg[i];
    g_dis[i] = d > 0 ? rsqrtf((float)d) : 0.0f;
}

__global__ void k_scan(int n) {
    __shared__ int ssum[1024];
    int tid = threadIdx.x;
    const int T = 1024;
    int chunk = (n + T - 1) / T;
    int beg = tid * chunk;
    int end = beg + chunk; if (end > n) end = n;
    int s = 0;
    for (int i = beg; i < end; i++) s += g_cnt[i];
    ssum[tid] = s;
    __syncthreads();
    for (int off = 1; off < T; off <<= 1) {
        int v = (tid >= off) ? ssum[tid - off] : 0;
        __syncthreads();
        ssum[tid] += v;
        __syncthreads();
    }
    int run = (tid > 0) ? ssum[tid - 1] : 0;
    for (int i = beg; i < end; i++) { g_roff[i] = run; run += g_cnt[i]; }
    if (tid == T - 1) g_roff[n] = ssum[T - 1];
}

__global__ void k_fill(const int* __restrict__ src, const int* __restrict__ dst, int E) {
    int e = blockIdx.x * blockDim.x + threadIdx.x;
    if (e >= E) return;
    int s = src[e], d = dst[e];
    int pos = g_roff[d] + atomicAdd(&g_cur[d], 1);
    g_csrc[pos] = s;
    g_cw[pos] = -g_dis[s] * g_dis[d];
}

// ====================== bf16 split helper ==================================

__device__ __forceinline__ void bsplit(float x, __nv_bfloat16& hi, __nv_bfloat16& lo) {
    hi = __float2bfloat16_rn(x);
    lo = __float2bfloat16_rn(x - __bfloat162float(hi));
}

// ====================== merged weight/bias preprocessing ===================
// B2 layout per GEMM: row stride 2*Kp; hi at [kk], lo at [Kp+kk].

__device__ __forceinline__ void prep_gateB(const float* __restrict__ Wx, int F, int H,
                                           int Kp, int nrow, int kk,
                                           __nv_bfloat16* __restrict__ dst) {
    int gp = nrow / H, o = nrow % H;
    int gate = (gp == 0) ? 0 : (gp + 1);   // gates {0,2,3}
    float w = 0.0f;
    if (kk < 3 * F) {
        int kc = kk / F, f = kk % F;
        w = Wx[(((size_t)gate * 3 + kc) * F + f) * H + o];
    }
    __nv_bfloat16 hi, lo; bsplit(w, hi, lo);
    dst[(size_t)nrow * 2 * Kp + kk] = hi;
    dst[(size_t)nrow * 2 * Kp + Kp + kk] = lo;
}

__device__ __forceinline__ void prep_linB(const float* __restrict__ W, int Hout,
                                          int Kp, int nrow, int kk,
                                          __nv_bfloat16* __restrict__ dst) {
    float w = W[(size_t)kk * Hout + nrow];
    __nv_bfloat16 hi, lo; bsplit(w, hi, lo);
    dst[(size_t)nrow * 2 * Kp + kk] = hi;
    dst[(size_t)nrow * 2 * Kp + Kp + kk] = lo;
}

#define E1 24576     // 768*32
#define E2 172032    // +384*384
#define E3 208896    // +192*192
#define E4 241664    // +128*256
#define E5 249856    // +64*128
#define E6 251200    // +1344 biases

__global__ void k_prep_all(
    const float* __restrict__ w1, const float* __restrict__ w2, const float* __restrict__ w3,
    const float* __restrict__ wl1, const float* __restrict__ wl2,
    const float* __restrict__ bx1, const float* __restrict__ bh1, const float* __restrict__ b1,
    const float* __restrict__ bx2, const float* __restrict__ bh2, const float* __restrict__ b2,
    const float* __restrict__ bx3, const float* __restrict__ bh3, const float* __restrict__ b3) {
    int idx = blockIdx.x * blockDim.x + threadIdx.x;
    if (idx >= E6) return;
    if (idx < E1) {
        prep_gateB(w1, 3, 256, 32, idx / 32, idx % 32, g_bbuf + O_B1);
    } else if (idx < E2) {
        int t = idx - E1;
        prep_gateB(w2, 128, 128, 384, t / 384, t % 384, g_bbuf + O_B2);
    } else if (idx < E3) {
        int t = idx - E2;
        prep_gateB(w3, 64, 64, 192, t / 192, t % 192, g_bbuf + O_B3);
    } else if (idx < E4) {
        int t = idx - E3;
        prep_linB(wl1, 128, 256, t / 256, t % 256, g_bbuf + O_BL1);
    } else if (idx < E5) {
        int t = idx - E4;
        prep_linB(wl2, 64, 128, t / 128, t % 128, g_bbuf + O_BL2);
    } else {
        int t = idx - E5;
        const float *bx, *bh, *bb; int H, base;
        if (t < 768)       { bx = bx1; bh = bh1; bb = b1; H = 256; base = 0; }
        else if (t < 1152) { bx = bx2; bh = bh2; bb = b2; H = 128; base = 768; t -= 768; }
        else               { bx = bx3; bh = bh3; bb = b3; H = 64;  base = 1152; t -= 1152; }
        int gp = t / H, o = t % H;
        int gate = (gp == 0) ? 0 : (gp + 1);
        g_wbias[base + t] = bx[gate * H + o] + bh[gate * H + o] + bb[gate * H + o];
    }
}

// ====================== layer-1 cheb prep (F=3) ============================
// A2 row layout (Kp=32): hi [T0(0-2) T1(3-5) T2(6-8) 0(9-31)], lo at +32.

__global__ void k_l1a(const float* __restrict__ x, float* __restrict__ t1d,
                      __nv_bfloat16* __restrict__ A2, int n, int npad) {
    int row = blockIdx.x * blockDim.x + threadIdx.x;
    if (row >= npad) return;
    float t0[3] = {0, 0, 0}, t1[3] = {0, 0, 0};
    if (row < n) {
        t0[0] = x[row * 3]; t0[1] = x[row * 3 + 1]; t0[2] = x[row * 3 + 2];
        int j0 = g_roff[row], j1 = g_roff[row + 1];
        for (int j = j0; j < j1; j++) {
            int sidx = g_csrc[j]; float w = g_cw[j];
            t1[0] += w * x[sidx * 3];
            t1[1] += w * x[sidx * 3 + 1];
            t1[2] += w * x[sidx * 3 + 2];
        }
        t1d[row * 3] = t1[0]; t1d[row * 3 + 1] = t1[1]; t1d[row * 3 + 2] = t1[2];
    }
    size_t base = (size_t)row * 64;
    __nv_bfloat16 hi, lo;
#pragma unroll
    for (int k = 0; k < 3; k++) {
        bsplit(t0[k], hi, lo);
        A2[base + k] = hi; A2[base + 32 + k] = lo;
        bsplit(t1[k], hi, lo);
        A2[base + 3 + k] = hi; A2[base + 35 + k] = lo;
    }
#pragma unroll
    for (int k = 9; k < 32; k++) {
        A2[base + k] = __float2bfloat16(0.f);
        A2[base + 32 + k] = __float2bfloat16(0.f);
    }
}

__global__ void k_l1b(const float* __restrict__ t1d, const float* __restrict__ x,
                      __nv_bfloat16* __restrict__ A2, int n, int npad) {
    int row = blockIdx.x * blockDim.x + threadIdx.x;
    if (row >= npad) return;
    float t2[3] = {0, 0, 0};
    if (row < n) {
        int j0 = g_roff[row], j1 = g_roff[row + 1];
        for (int j = j0; j < j1; j++) {
            int sidx = g_csrc[j]; float w = g_cw[j];
            t2[0] += w * t1d[sidx * 3];
            t2[1] += w * t1d[sidx * 3 + 1];
            t2[2] += w * t1d[sidx * 3 + 2];
        }
        t2[0] = 2.f * t2[0] - x[row * 3];
        t2[1] = 2.f * t2[1] - x[row * 3 + 1];
        t2[2] = 2.f * t2[2] - x[row * 3 + 2];
    }
    size_t base = (size_t)row * 64;
    __nv_bfloat16 hi, lo;
#pragma unroll
    for (int k = 0; k < 3; k++) {
        bsplit(t2[k], hi, lo);
        A2[base + 6 + k] = hi; A2[base + 38 + k] = lo;
    }
}

// ====================== fused SpMV + split =================================
// y = L x (or 2 L x - x0); writes dense fp32 (if Yd) + split into A2 section.

template <int F, int CHEB2>
__global__ void k_spmv_split(const float* __restrict__ X, const float* __restrict__ X0,
                             float* __restrict__ Yd,
                             __nv_bfloat16* __restrict__ A2, int Kp, int sec,
                             int n, int npad) {
    const int TPR = F / 4;
    int tid = threadIdx.x;
    int row = blockIdx.x * (256 / TPR) + tid / TPR;
    int f = (tid % TPR) * 4;
    if (row >= npad) return;
    float a0 = 0.f, a1 = 0.f, a2 = 0.f, a3 = 0.f;
    if (row < n) {
        int j0 = g_roff[row], j1 = g_roff[row + 1];
        for (int j = j0; j < j1; j++) {
            int sidx = g_csrc[j]; float w = g_cw[j];
            float4 xv = *reinterpret_cast<const float4*>(X + (size_t)sidx * F + f);
            a0 += w * xv.x; a1 += w * xv.y; a2 += w * xv.z; a3 += w * xv.w;
        }
        if (CHEB2) {
            float4 x0 = *reinterpret_cast<const float4*>(X0 + (size_t)row * F + f);
            a0 = 2.f * a0 - x0.x; a1 = 2.f * a1 - x0.y;
            a2 = 2.f * a2 - x0.z; a3 = 2.f * a3 - x0.w;
        }
        if (Yd)
            *reinterpret_cast<float4*>(Yd + (size_t)row * F + f) = make_float4(a0, a1, a2, a3);
    }
    __nv_bfloat16 h0, l0, h1, l1, h2, l2, h3, l3;
    bsplit(a0, h0, l0); bsplit(a1, h1, l1); bsplit(a2, h2, l2); bsplit(a3, h3, l3);
    size_t base = (size_t)row * 2 * Kp + sec + f;
    __nv_bfloat162* ph = reinterpret_cast<__nv_bfloat162*>(A2 + base);
    ph[0] = __nv_bfloat162(h0, h1); ph[1] = __nv_bfloat162(h2, h3);
    __nv_bfloat162* pl = reinterpret_cast<__nv_bfloat162*>(A2 + base + Kp);
    pl[0] = __nv_bfloat162(l0, l1); pl[1] = __nv_bfloat162(l2, l3);
}

// ====================== mma.sync split-bf16 GEMM ===========================
// C[M,Nc] = A @ B^T with A=[Ahi|Alo], B=[Bhi|Blo] (row stride 2*Kp, K-major).
// acc += Ahi*Bhi + Ahi*Blo + Alo*Bhi. CTA tile 128x64, BK=32, 8 warps (4x2).
// Grid: x = N-tiles (fast, for L2 A-reuse across wave), y = M-tiles.
// Optional fused epilogue: bias, leaky-relu, fp32 store, bf16-split store.

#define CP16(dst, src) \
    asm volatile("cp.async.ca.shared.global [%0], [%1], 16;\n" :: "r"(dst), "l"(src))
#define CP_COMMIT() asm volatile("cp.async.commit_group;\n" ::: "memory")
#define CP_WAIT1()  asm volatile("cp.async.wait_group 1;\n" ::: "memory")
#define CP_WAIT0()  asm volatile("cp.async.wait_group 0;\n" ::: "memory")

__device__ __forceinline__ uint32_t smem_u32(const void* p) {
    uint32_t a;
    asm("{ .reg .u64 t; cvta.to.shared.u64 t, %1; cvt.u32.u64 %0, t; }"
        : "=r"(a) : "l"(p));
    return a;
}

__device__ __forceinline__ void ldm_x4(uint32_t* r, uint32_t addr) {
    asm volatile("ldmatrix.sync.aligned.m8n8.x4.shared.b16 {%0,%1,%2,%3}, [%4];"
                 : "=r"(r[0]), "=r"(r[1]), "=r"(r[2]), "=r"(r[3]) : "r"(addr));
}

__device__ __forceinline__ void mma16816(float* c, const uint32_t* a, const uint32_t* b) {
    asm volatile(
        "mma.sync.aligned.m16n8k16.row.col.f32.bf16.bf16.f32 "
        "{%0,%1,%2,%3}, {%4,%5,%6,%7}, {%8,%9}, {%0,%1,%2,%3};"
        : "+f"(c[0]), "+f"(c[1]), "+f"(c[2]), "+f"(c[3])
        : "r"(a[0]), "r"(a[1]), "r"(a[2]), "r"(a[3]), "r"(b[0]), "r"(b[1]));
}

// smem stage layout (80B padded rows): A-hi rows 0-127, A-lo 128-255,
// B-hi 256-319, B-lo 320-383. Stage size = 384*80 = 30720B, 2 stages.
#define GSTAGE 30720

__global__ __launch_bounds__(256) void gemm_mma2(
    const __nv_bfloat16* __restrict__ A, const __nv_bfloat16* __restrict__ B,
    const float* __restrict__ bias, float* __restrict__ C,
    __nv_bfloat16* __restrict__ S, int sKp,
    int M, int Kp, int Nc, int act) {
    extern __shared__ char smem[];
    const uint32_t s0 = smem_u32(smem);
    const int tid = threadIdx.x;
    const int wid = tid >> 5;
    const int lane = tid & 31;
    const int wm = wid & 3, wn = wid >> 2;
    const int bn = blockIdx.x << 6;
    const int bm = blockIdx.y << 7;
    const size_t strA = 2 * (size_t)Kp;

    float acc[2][4][4];
#pragma unroll
    for (int i = 0; i < 2; i++)
#pragma unroll
        for (int j = 0; j < 4; j++)
#pragma unroll
            for (int k = 0; k < 4; k++) acc[i][j][k] = 0.f;

#define LOAD_STAGE(stg, kc) do {                                             \
    uint32_t dstBase = s0 + (stg) * GSTAGE;                                  \
    _Pragma("unroll")                                                        \
    for (int u = tid; u < 1536; u += 256) {                                  \
        uint32_t d; const char* g;                                           \
        if (u < 1024) {                                                      \
            int hl = u >> 9, t = u & 511, row = t >> 2, seg = t & 3;         \
            d = dstBase + (hl * 128 + row) * 80 + seg * 16;                  \
            g = (const char*)A + ((size_t)(bm + row) * strA                  \
                + (size_t)hl * Kp + (kc)) * 2 + seg * 16;                    \
        } else {                                                             \
            int t = u - 1024; int hl = t >> 8; t &= 255;                     \
            int row = t >> 2, seg = t & 3;                                   \
            d = dstBase + (256 + hl * 64 + row) * 80 + seg * 16;             \
            g = (const char*)B + ((size_t)(bn + row) * strA                  \
                + (size_t)hl * Kp + (kc)) * 2 + seg * 16;                    \
        }                                                                    \
        CP16(d, g);                                                          \
    } } while (0)

    const int nK = Kp >> 5;
    LOAD_STAGE(0, 0);
    CP_COMMIT();

    for (int kt = 0; kt < nK; kt++) {
        int st = kt & 1;
        if (kt + 1 < nK) {
            LOAD_STAGE((kt + 1) & 1, (kt + 1) << 5);
            CP_COMMIT();
            CP_WAIT1();
        } else {
            CP_WAIT0();
        }
        __syncthreads();
        uint32_t base = s0 + st * GSTAGE;
        uint32_t kb = (lane >> 4) * 16;
        uint32_t arow = wm * 32 + (lane & 15);
        uint32_t brow = 256 + wn * 32 + (lane & 15);
#pragma unroll
        for (int kk = 0; kk < 2; kk++) {
            uint32_t a_hi[2][4], a_lo[2][4];
#pragma unroll
            for (int mt = 0; mt < 2; mt++) {
                ldm_x4(a_hi[mt], base + (arow + mt * 16) * 80 + kk * 32 + kb);
                ldm_x4(a_lo[mt], base + (arow + mt * 16 + 128) * 80 + kk * 32 + kb);
            }
            uint32_t b_hi[4][2], b_lo[4][2];
#pragma unroll
            for (int j = 0; j < 2; j++) {
                uint32_t r[4];
                ldm_x4(r, base + (brow + j * 16) * 80 + kk * 32 + kb);
                b_hi[2 * j][0] = r[0]; b_hi[2 * j][1] = r[2];
                b_hi[2 * j + 1][0] = r[1]; b_hi[2 * j + 1][1] = r[3];
                ldm_x4(r, base + (brow + j * 16 + 64) * 80 + kk * 32 + kb);
                b_lo[2 * j][0] = r[0]; b_lo[2 * j][1] = r[2];
                b_lo[2 * j + 1][0] = r[1]; b_lo[2 * j + 1][1] = r[3];
            }
#pragma unroll
            for (int mt = 0; mt < 2; mt++)
#pragma unroll
                for (int nt = 0; nt < 4; nt++) {
                    mma16816(acc[mt][nt], a_hi[mt], b_hi[nt]);
                    mma16816(acc[mt][nt], a_hi[mt], b_lo[nt]);
                    mma16816(acc[mt][nt], a_lo[mt], b_hi[nt]);
                }
        }
        __syncthreads();
    }

    // epilogue
    const int gid = lane >> 2, tig = lane & 3;
#pragma unroll
    for (int mt = 0; mt < 2; mt++) {
#pragma unroll
        for (int half = 0; half < 2; half++) {
            int row = bm + wm * 32 + mt * 16 + half * 8 + gid;
            bool valid = row < M;
#pragma unroll
            for (int nt = 0; nt < 4; nt++) {
                int col = bn + wn * 32 + nt * 8 + tig * 2;
                float v0 = 0.f, v1 = 0.f;
                if (valid) {
                    v0 = acc[mt][nt][2 * half + 0] + bias[col];
                    v1 = acc[mt][nt][2 * half + 1] + bias[col + 1];
                    if (act) {
                        v0 = v0 > 0.f ? v0 : 0.1f * v0;
                        v1 = v1 > 0.f ? v1 : 0.1f * v1;
                    }
                    *reinterpret_cast<float2*>(&C[(size_t)row * Nc + col]) =
                        make_float2(v0, v1);
                }
                if (S) {
                    __nv_bfloat16 h0, l0, h1, l1;
                    bsplit(v0, h0, l0); bsplit(v1, h1, l1);
                    size_t sb = (size_t)row * 2 * sKp + col;
                    *reinterpret_cast<__nv_bfloat162*>(S + sb) = __nv_bfloat162(h0, h1);
                    *reinterpret_cast<__nv_bfloat162*>(S + sb + sKp) = __nv_bfloat162(l0, l1);
                }
            }
        }
    }
}

// ====================== LSTM gate fusion ===================================

__device__ __forceinline__ float sigf(float x) { return 1.0f / (1.0f + expf(-x)); }

__device__ __forceinline__ float gate_eval(const float* g, const float* wcO, int H, int o) {
    float I = sigf(g[o]);
    float T = tanhf(g[H + o]);
    float Cv = I * T;
    float O = sigf(g[2 * H + o] + wcO[o] * Cv);
    float y = O * tanhf(Cv);
    return y > 0.f ? y : 0.1f * y;   // fused leaky relu
}

__global__ void k_gates(const float* __restrict__ G, const float* __restrict__ wcO,
                        float* __restrict__ Y, int n, int H) {
    int idx = blockIdx.x * blockDim.x + threadIdx.x;
    if (idx >= n * H) return;
    int r = idx / H, o = idx % H;
    Y[(size_t)r * H + o] = gate_eval(G + (size_t)r * 3 * H, wcO, H, o);
}

// gates -> [hi|lo] split A2 (Kp == H)
__global__ void k_gates_split(const float* __restrict__ G, const float* __restrict__ wcO,
                              __nv_bfloat16* __restrict__ A2, int n, int npad, int H) {
    int idx = blockIdx.x * blockDim.x + threadIdx.x;
    if (idx >= npad * H) return;
    int r = idx / H, o = idx % H;
    float y = 0.0f;
    if (r < n) y = gate_eval(G + (size_t)r * 3 * H, wcO, H, o);
    __nv_bfloat16 hi, lo; bsplit(y, hi, lo);
    size_t base = (size_t)r * 2 * H;
    A2[base + o] = hi;
    A2[base + H + o] = lo;
}

// ====================== final small GEMM [N,64]@[64,3] =====================

__global__ void k_lin3(const float* __restrict__ Hin, const float* __restrict__ W,
                       const float* __restrict__ b, float* __restrict__ out, int n) {
    __shared__ float w[64 * 3];
    if (threadIdx.x < 192) w[threadIdx.x] = W[threadIdx.x];
    __syncthreads();
    int r = blockIdx.x * blockDim.x + threadIdx.x;
    if (r >= n) return;
    float a0 = b[0], a1 = b[1], a2 = b[2];
    const float* h = Hin + (size_t)r * 64;
#pragma unroll
    for (int k = 0; k < 64; k++) {
        float hv = h[k];
        a0 += hv * w[k * 3 + 0];
        a1 += hv * w[k * 3 + 1];
        a2 += hv * w[k * 3 + 2];
    }
    float* o = out + (size_t)r * 3;
    o[0] = a0; o[1] = a1; o[2] = a2;
}

// ====================== host orchestration =================================

static inline int ceildiv(int a, int b) { return (a + b - 1) / b; }

extern "C" void kernel_launch(void* const* d_in, const int* in_sizes, int n_in,
                              void* d_out, int out_size) {
    const float* x = (const float*)d_in[0];
    const int* ei = (const int*)d_in[1];
    int N = in_sizes[0] / 3;
    int E = in_sizes[1] / 2;
    const int* src = ei;
    const int* dst = ei + E;
    int Npad = (N + 127) & ~127;
    int Mt = Npad / 128;

    const float* l1_Wx = (const float*)d_in[2];
    const float* l1_bx = (const float*)d_in[3];
    const float* l1_bh = (const float*)d_in[5];
    const float* l1_wc = (const float*)d_in[6];
    const float* l1_b  = (const float*)d_in[7];
    const float* l2_Wx = (const float*)d_in[8];
    const float* l2_bx = (const float*)d_in[9];
    const float* l2_bh = (const float*)d_in[11];
    const float* l2_wc = (const float*)d_in[12];
    const float* l2_b  = (const float*)d_in[13];
    const float* l3_Wx = (const float*)d_in[14];
    const float* l3_bx = (const float*)d_in[15];
    const float* l3_bh = (const float*)d_in[17];
    const float* l3_wc = (const float*)d_in[18];
    const float* l3_b  = (const float*)d_in[19];
    const float* lin1_W = (const float*)d_in[20];
    const float* lin1_b = (const float*)d_in[21];
    const float* lin2_W = (const float*)d_in[22];
    const float* lin2_b = (const float*)d_in[23];
    const float* lin3_W = (const float*)d_in[24];
    const float* lin3_b = (const float*)d_in[25];
    float* out = (float*)d_out;

    void* p;
    cudaGetSymbolAddress(&p, g_deg);   int* deg = (int*)p;
    cudaGetSymbolAddress(&p, g_cnt);   int* cnt = (int*)p;
    cudaGetSymbolAddress(&p, g_cur);   int* cur = (int*)p;
    cudaGetSymbolAddress(&p, g_xc);    float* xc = (float*)p;
    cudaGetSymbolAddress(&p, g_gate);  float* G = (float*)p;
    cudaGetSymbolAddress(&p, g_h);     float* Hbuf = (float*)p;
    cudaGetSymbolAddress(&p, g_h2);    float* H2 = (float*)p;
    cudaGetSymbolAddress(&p, g_wbias); float* wb = (float*)p;
    cudaGetSymbolAddress(&p, g_bufA);  __nv_bfloat16* bufA = (__nv_bfloat16*)p;
    cudaGetSymbolAddress(&p, g_bufB);  __nv_bfloat16* bufB = (__nv_bfloat16*)p;
    cudaGetSymbolAddress(&p, g_bbuf);  __nv_bfloat16* bb = (__nv_bfloat16*)p;

    cudaFuncSetAttribute(gemm_mma2, cudaFuncAttributeMaxDynamicSharedMemorySize,
                         2 * GSTAGE);

    cudaStream_t s = 0;

    // ---- graph preprocessing ----
    cudaMemsetAsync(deg, 0, N * sizeof(int), s);
    cudaMemsetAsync(cnt, 0, N * sizeof(int), s);
    cudaMemsetAsync(cur, 0, N * sizeof(int), s);
    k_degree<<<ceildiv(E, 256), 256, 0, s>>>(src, dst, E);
    k_dis<<<ceildiv(N, 256), 256, 0, s>>>(N);
    k_scan<<<1, 1024, 0, s>>>(N);
    k_fill<<<ceildiv(E, 256), 256, 0, s>>>(src, dst, E);

    // ---- all weight/bias preprocessing in one kernel ----
    k_prep_all<<<ceildiv(E6, 256), 256, 0, s>>>(
        l1_Wx, l2_Wx, l3_Wx, lin1_W, lin2_W,
        l1_bx, l1_bh, l1_b, l2_bx, l2_bh, l2_b, l3_bx, l3_bh, l3_b);

    // ================= layer 1 (F=3, H=256) =================
    k_l1a<<<ceildiv(Npad, 256), 256, 0, s>>>(x, xc, bufA, N, Npad);
    k_l1b<<<ceildiv(Npad, 256), 256, 0, s>>>(xc, x, bufA, N, Npad);
    gemm_mma2<<<dim3(768 / 64, Mt), 256, 2 * GSTAGE, s>>>(
        bufA, bb + O_B1, wb, G, nullptr, 0, N, 32, 768, 0);
    k_gates_split<<<ceildiv(Npad * 256, 256), 256, 0, s>>>(G, l1_wc + 512, bufB, N, Npad, 256);
    // lin1: [N,256]@[256,128] + lrelu, fused split of T0 (layer2 Kp=384)
    gemm_mma2<<<dim3(128 / 64, Mt), 256, 2 * GSTAGE, s>>>(
        bufB, bb + O_BL1, lin1_b, H2, bufA, 384, N, 256, 128, 1);

    // ================= layer 2 (F=128, H=128) =================
    k_spmv_split<128, 0><<<ceildiv(Npad, 8), 256, 0, s>>>(H2, nullptr, xc, bufA, 384, 128, N, Npad);
    k_spmv_split<128, 1><<<ceildiv(Npad, 8), 256, 0, s>>>(xc, H2, nullptr, bufA, 384, 256, N, Npad);
    gemm_mma2<<<dim3(384 / 64, Mt), 256, 2 * GSTAGE, s>>>(
        bufA, bb + O_B2, wb + 768, G, nullptr, 0, N, 384, 384, 0);
    k_gates_split<<<ceildiv(Npad * 128, 256), 256, 0, s>>>(G, l2_wc + 256, bufB, N, Npad, 128);
    // lin2: [N,128]@[128,64] + lrelu, fused split of T0 (layer3 Kp=192)
    gemm_mma2<<<dim3(64 / 64, Mt), 256, 2 * GSTAGE, s>>>(
        bufB, bb + O_BL2, lin2_b, H2, bufA, 192, N, 128, 64, 1);

    // ================= layer 3 (F=64, H=64) =================
    k_spmv_split<64, 0><<<ceildiv(Npad, 16), 256, 0, s>>>(H2, nullptr, xc, bufA, 192, 64, N, Npad);
    k_spmv_split<64, 1><<<ceildiv(Npad, 16), 256, 0, s>>>(xc, H2, nullptr, bufA, 192, 128, N, Npad);
    gemm_mma2<<<dim3(192 / 64, Mt), 256, 2 * GSTAGE, s>>>(
        bufA, bb + O_B3, wb + 1152, G, nullptr, 0, N, 192, 192, 0);
    k_gates<<<ceildiv(N * 64, 256), 256, 0, s>>>(G, l3_wc + 128, Hbuf, N, 64);
    k_lin3<<<ceildiv(N, 256), 256, 0, s>>>(Hbuf, lin3_W, lin3_b, out, N);
}